// round 1
// baseline (speedup 1.0000x reference)
#include <cuda_runtime.h>
#include <cuda_bf16.h>
#include <cstdint>
#include <cstdio>

// Problem constants (fixed by the dataset)
#define BB 4
#define HH 16
#define LL 2048
#define DM 1024
#define DHEAD 64

// Scratch (allocation-free rule: __device__ globals)
__device__ float g_Q[(size_t)BB * HH * LL * DHEAD];     // 33.5 MB
__device__ float g_K[(size_t)BB * HH * LL * DHEAD];
__device__ float g_V[(size_t)BB * HH * LL * DHEAD];
__device__ float g_ctx[(size_t)BB * LL * (HH * DHEAD)]; // 33.5 MB
__device__ float g_attn_scratch[(size_t)BB * HH * LL * LL]; // 1.07 GB fallback if attn not in d_out

// ---------------------------------------------------------------------------
// Projection: Out[b,h,s,e] = sum_d X[b,s,d] * W[h,d,e]
// Per (b,h): GEMM (2048 x 1024) @ (1024 x 64). Block tile 64x64 (full N), BK=16.
// grid = (32, 16, 4), block = 256
// ---------------------------------------------------------------------------
__global__ void proj_kernel(const float* __restrict__ X,
                            const float* __restrict__ W,
                            float* __restrict__ O)
{
    const int b = blockIdx.z;
    const int h = blockIdx.y;
    const int i0 = blockIdx.x * 64;

    const float* A  = X + (size_t)b * LL * DM;            // (2048 x 1024) row-major
    const float* Bw = W + (size_t)h * DM * DHEAD;         // (1024 x 64) row-major
    float* Out = O + ((size_t)(b * HH + h) * LL) * DHEAD; // (2048 x 64)

    __shared__ float As[64][17];
    __shared__ float Bs[16][64];

    const int tid = threadIdx.x;
    const int tx = tid & 15, ty = tid >> 4;

    float acc[4][4] = {};

    for (int k0 = 0; k0 < DM; k0 += 16) {
        // A tile: 64x16, one float4 per thread
        {
            int r = tid >> 2, c = (tid & 3) << 2;
            float4 v = *(const float4*)&A[(size_t)(i0 + r) * DM + k0 + c];
            As[r][c] = v.x; As[r][c + 1] = v.y; As[r][c + 2] = v.z; As[r][c + 3] = v.w;
        }
        // B tile: 16x64, one float4 per thread
        {
            int r = tid >> 4, c = (tid & 15) << 2;
            *(float4*)&Bs[r][c] = *(const float4*)&Bw[(size_t)(k0 + r) * DHEAD + c];
        }
        __syncthreads();
        #pragma unroll
        for (int kk = 0; kk < 16; kk++) {
            float a[4];
            #pragma unroll
            for (int i = 0; i < 4; i++) a[i] = As[(ty << 2) + i][kk];
            float4 b4 = *(const float4*)&Bs[kk][tx << 2];
            float bb[4] = {b4.x, b4.y, b4.z, b4.w};
            #pragma unroll
            for (int i = 0; i < 4; i++)
                #pragma unroll
                for (int j = 0; j < 4; j++)
                    acc[i][j] += a[i] * bb[j];
        }
        __syncthreads();
    }
    #pragma unroll
    for (int i = 0; i < 4; i++) {
        int row = i0 + (ty << 2) + i;
        float4 o = make_float4(acc[i][0], acc[i][1], acc[i][2], acc[i][3]);
        *(float4*)&Out[(size_t)row * DHEAD + (tx << 2)] = o;
    }
}

// ---------------------------------------------------------------------------
// Scores: S[z, i, j] = scale * sum_e Q[z,i,e] * K[z,j,e]  (pre-softmax)
// Per block: 64x64 output tile; e-dim (=64) fits entirely in smem.
// grid = (32 jtiles, 32 itiles, 64 z), block = 256
// ---------------------------------------------------------------------------
__global__ void score_kernel(const float* __restrict__ Qp,
                             const float* __restrict__ Kp,
                             float* __restrict__ Sout)
{
    const int z = blockIdx.z;
    const int i0 = blockIdx.y * 64, j0 = blockIdx.x * 64;

    const float* Q = Qp + (size_t)z * LL * DHEAD;
    const float* K = Kp + (size_t)z * LL * DHEAD;
    float* S = Sout + (size_t)z * LL * LL;

    __shared__ float Qs[64][65];
    __shared__ float Ks[64][65];

    const int tid = threadIdx.x;
    const int tx = tid & 15, ty = tid >> 4;

    // Load both 64x64 tiles (1024 float4 each; 4 per thread)
    for (int t = tid; t < 1024; t += 256) {
        int r = t >> 4, c = (t & 15) << 2;
        float4 vq = *(const float4*)&Q[(size_t)(i0 + r) * DHEAD + c];
        Qs[r][c] = vq.x; Qs[r][c + 1] = vq.y; Qs[r][c + 2] = vq.z; Qs[r][c + 3] = vq.w;
        float4 vk = *(const float4*)&K[(size_t)(j0 + r) * DHEAD + c];
        Ks[r][c] = vk.x; Ks[r][c + 1] = vk.y; Ks[r][c + 2] = vk.z; Ks[r][c + 3] = vk.w;
    }
    __syncthreads();

    float acc[4][4] = {};
    #pragma unroll 8
    for (int e = 0; e < 64; e++) {
        float a[4], bb[4];
        #pragma unroll
        for (int i = 0; i < 4; i++) a[i] = Qs[(ty << 2) + i][e];
        #pragma unroll
        for (int j = 0; j < 4; j++) bb[j] = Ks[(tx << 2) + j][e];
        #pragma unroll
        for (int i = 0; i < 4; i++)
            #pragma unroll
            for (int j = 0; j < 4; j++)
                acc[i][j] += a[i] * bb[j];
    }

    const float scale = 0.125f; // 1/sqrt(64)
    #pragma unroll
    for (int i = 0; i < 4; i++) {
        int row = i0 + (ty << 2) + i;
        float4 o = make_float4(acc[i][0] * scale, acc[i][1] * scale,
                               acc[i][2] * scale, acc[i][3] * scale);
        *(float4*)&S[(size_t)row * LL + j0 + (tx << 2)] = o;
    }
}

// ---------------------------------------------------------------------------
// Row softmax over 2048 elements, in place. One block (256 thr) per row.
// grid = (B*H*L = 131072), block = 256
// ---------------------------------------------------------------------------
__global__ void softmax_kernel(float* __restrict__ S)
{
    float* p = S + (size_t)blockIdx.x * LL;
    const int tid = threadIdx.x;
    const int warp = tid >> 5, lane = tid & 31;
    __shared__ float red[8];

    float v[8];
    float m = -1e30f;
    #pragma unroll
    for (int i = 0; i < 8; i++) {
        v[i] = p[tid + (i << 8)];
        m = fmaxf(m, v[i]);
    }
    #pragma unroll
    for (int o = 16; o > 0; o >>= 1) m = fmaxf(m, __shfl_xor_sync(0xffffffffu, m, o));
    if (lane == 0) red[warp] = m;
    __syncthreads();
    if (tid < 8) {
        float t = red[tid];
        #pragma unroll
        for (int o = 4; o > 0; o >>= 1) t = fmaxf(t, __shfl_xor_sync(0xffu, t, o));
        if (tid == 0) red[0] = t;
    }
    __syncthreads();
    m = red[0];
    __syncthreads();

    float s = 0.0f;
    #pragma unroll
    for (int i = 0; i < 8; i++) {
        v[i] = __expf(v[i] - m);
        s += v[i];
    }
    #pragma unroll
    for (int o = 16; o > 0; o >>= 1) s += __shfl_xor_sync(0xffffffffu, s, o);
    if (lane == 0) red[warp] = s;
    __syncthreads();
    if (tid < 8) {
        float t = red[tid];
        #pragma unroll
        for (int o = 4; o > 0; o >>= 1) t += __shfl_xor_sync(0xffu, t, o);
        if (tid == 0) red[0] = t;
    }
    __syncthreads();
    float inv = 1.0f / red[0];

    #pragma unroll
    for (int i = 0; i < 8; i++)
        p[tid + (i << 8)] = v[i] * inv;
}

// ---------------------------------------------------------------------------
// ctx: per (b,h): C (2048 x 64) = attn (2048 x 2048) @ V (2048 x 64)
// Written to ctx[b][q][h*64 + e] layout for the final GEMM.
// grid = (32 itiles, 1, 64 z), block = 256
// ---------------------------------------------------------------------------
__global__ void ctx_kernel(const float* __restrict__ Sm,
                           const float* __restrict__ Vp,
                           float* __restrict__ Ctx)
{
    const int z = blockIdx.z;
    const int b = z >> 4, h = z & 15;
    const int i0 = blockIdx.x * 64;

    const float* A = Sm + (size_t)z * LL * LL;
    const float* V = Vp + (size_t)z * LL * DHEAD;

    __shared__ float As[64][17];
    __shared__ float Bs[16][64];

    const int tid = threadIdx.x;
    const int tx = tid & 15, ty = tid >> 4;

    float acc[4][4] = {};

    for (int k0 = 0; k0 < LL; k0 += 16) {
        {
            int r = tid >> 2, c = (tid & 3) << 2;
            float4 v = *(const float4*)&A[(size_t)(i0 + r) * LL + k0 + c];
            As[r][c] = v.x; As[r][c + 1] = v.y; As[r][c + 2] = v.z; As[r][c + 3] = v.w;
        }
        {
            int r = tid >> 4, c = (tid & 15) << 2;
            *(float4*)&Bs[r][c] = *(const float4*)&V[(size_t)(k0 + r) * DHEAD + c];
        }
        __syncthreads();
        #pragma unroll
        for (int kk = 0; kk < 16; kk++) {
            float a[4];
            #pragma unroll
            for (int i = 0; i < 4; i++) a[i] = As[(ty << 2) + i][kk];
            float4 b4 = *(const float4*)&Bs[kk][tx << 2];
            float bb[4] = {b4.x, b4.y, b4.z, b4.w};
            #pragma unroll
            for (int i = 0; i < 4; i++)
                #pragma unroll
                for (int j = 0; j < 4; j++)
                    acc[i][j] += a[i] * bb[j];
        }
        __syncthreads();
    }
    #pragma unroll
    for (int i = 0; i < 4; i++) {
        int row = i0 + (ty << 2) + i;
        float4 o = make_float4(acc[i][0], acc[i][1], acc[i][2], acc[i][3]);
        *(float4*)&Ctx[((size_t)b * LL + row) * (HH * DHEAD) + h * DHEAD + (tx << 2)] = o;
    }
}

// ---------------------------------------------------------------------------
// out: (B*LQ x 1024) = ctx (B*LQ x 1024) @ wo (1024 x 1024)
// grid = (16 jtiles, 128 itiles), block = 256
// ---------------------------------------------------------------------------
__global__ void out_kernel(const float* __restrict__ Ctx,
                           const float* __restrict__ Wo,
                           float* __restrict__ Out)
{
    const int i0 = blockIdx.y * 64, j0 = blockIdx.x * 64;
    const int NN = HH * DHEAD; // 1024

    __shared__ float As[64][17];
    __shared__ float Bs[16][64];

    const int tid = threadIdx.x;
    const int tx = tid & 15, ty = tid >> 4;

    float acc[4][4] = {};

    for (int k0 = 0; k0 < NN; k0 += 16) {
        {
            int r = tid >> 2, c = (tid & 3) << 2;
            float4 v = *(const float4*)&Ctx[(size_t)(i0 + r) * NN + k0 + c];
            As[r][c] = v.x; As[r][c + 1] = v.y; As[r][c + 2] = v.z; As[r][c + 3] = v.w;
        }
        {
            int r = tid >> 4, c = (tid & 15) << 2;
            *(float4*)&Bs[r][c] = *(const float4*)&Wo[(size_t)(k0 + r) * DM + j0 + c];
        }
        __syncthreads();
        #pragma unroll
        for (int kk = 0; kk < 16; kk++) {
            float a[4];
            #pragma unroll
            for (int i = 0; i < 4; i++) a[i] = As[(ty << 2) + i][kk];
            float4 b4 = *(const float4*)&Bs[kk][tx << 2];
            float bb[4] = {b4.x, b4.y, b4.z, b4.w};
            #pragma unroll
            for (int i = 0; i < 4; i++)
                #pragma unroll
                for (int j = 0; j < 4; j++)
                    acc[i][j] += a[i] * bb[j];
        }
        __syncthreads();
    }
    #pragma unroll
    for (int i = 0; i < 4; i++) {
        int row = i0 + (ty << 2) + i;
        float4 o = make_float4(acc[i][0], acc[i][1], acc[i][2], acc[i][3]);
        *(float4*)&Out[(size_t)row * DM + j0 + (tx << 2)] = o;
    }
}

// ---------------------------------------------------------------------------
extern "C" void kernel_launch(void* const* d_in, const int* in_sizes, int n_in,
                              void* d_out, int out_size)
{
    const float* q  = (const float*)d_in[0];
    const float* k  = (const float*)d_in[1];
    const float* v  = (const float*)d_in[2];
    const float* wq = (const float*)d_in[3];
    const float* wk = (const float*)d_in[4];
    const float* wv = (const float*)d_in[5];
    const float* wo = (const float*)d_in[6];

    float* out = (float*)d_out;

    const size_t OUT_ELEMS  = (size_t)BB * LL * DM;       // 8,388,608
    const size_t ATTN_ELEMS = (size_t)BB * HH * LL * LL;  // 268,435,456

    float *gQ, *gK, *gV, *gCtx, *attn;
    cudaGetSymbolAddress((void**)&gQ, g_Q);
    cudaGetSymbolAddress((void**)&gK, g_K);
    cudaGetSymbolAddress((void**)&gV, g_V);
    cudaGetSymbolAddress((void**)&gCtx, g_ctx);

    // Output contract: reference returns (out, attn). If d_out has room for
    // both, write attn into d_out after out; otherwise attn is scratch-only.
    if ((size_t)(unsigned)out_size >= OUT_ELEMS + ATTN_ELEMS) {
        attn = out + OUT_ELEMS;
    } else {
        cudaGetSymbolAddress((void**)&attn, g_attn_scratch);
    }

    dim3 blk(256);
    proj_kernel<<<dim3(LL / 64, HH, BB), blk>>>(q, wq, gQ);
    proj_kernel<<<dim3(LL / 64, HH, BB), blk>>>(k, wk, gK);
    proj_kernel<<<dim3(LL / 64, HH, BB), blk>>>(v, wv, gV);

    score_kernel<<<dim3(LL / 64, LL / 64, BB * HH), blk>>>(gQ, gK, attn);
    softmax_kernel<<<dim3(BB * HH * LL), blk>>>(attn);
    ctx_kernel<<<dim3(LL / 64, 1, BB * HH), blk>>>(attn, gV, gCtx);
    out_kernel<<<dim3(DM / 64, (BB * LL) / 64), blk>>>(gCtx, wo, out);
}

// round 2
// speedup vs baseline: 1.2240x; 1.2240x over previous
#include <cuda_runtime.h>
#include <cuda_bf16.h>
#include <cstdint>

#define BB 4
#define HH 16
#define LL 2048
#define DM 1024
#define DHEAD 64

// Scratch (__device__ globals; allocation-free rule)
__device__ float g_Q[(size_t)BB * HH * LL * DHEAD];
__device__ float g_K[(size_t)BB * HH * LL * DHEAD];
__device__ float g_V[(size_t)BB * HH * LL * DHEAD];
__device__ float g_ctx[(size_t)BB * LL * (HH * DHEAD)];
__device__ float g_attn_scratch[(size_t)BB * HH * LL * LL]; // fallback if attn not in d_out

// ---------------------------------------------------------------------------
// proj: Out[b,h,s,e] = sum_d X[b,s,d] * W[h,d,e]
// 128x64 block tile, 8x4 per thread, BK=16. A stored transposed in smem.
// grid = (16, 16, 4), block = 256
// ---------------------------------------------------------------------------
__global__ __launch_bounds__(256) void proj_v2(const float* __restrict__ X,
                                               const float* __restrict__ W,
                                               float* __restrict__ O)
{
    const int b = blockIdx.z, h = blockIdx.y, i0 = blockIdx.x * 128;
    const float* A  = X + (size_t)b * LL * DM;
    const float* Bw = W + (size_t)h * DM * DHEAD;
    float* Out = O + ((size_t)(b * HH + h) * LL + i0) * DHEAD;

    __shared__ float Ast[16][132]; // [k][row]
    __shared__ float Bs[16][64];

    const int tid = threadIdx.x, tx = tid & 15, ty = tid >> 4;
    const int ar = tid >> 1, ac0 = (tid & 1) * 8;

    float acc[8][4] = {};

    for (int k0 = 0; k0 < DM; k0 += 16) {
        float4 a0 = *(const float4*)&A[(size_t)(i0 + ar) * DM + k0 + ac0];
        float4 a1 = *(const float4*)&A[(size_t)(i0 + ar) * DM + k0 + ac0 + 4];
        Ast[ac0 + 0][ar] = a0.x; Ast[ac0 + 1][ar] = a0.y;
        Ast[ac0 + 2][ar] = a0.z; Ast[ac0 + 3][ar] = a0.w;
        Ast[ac0 + 4][ar] = a1.x; Ast[ac0 + 5][ar] = a1.y;
        Ast[ac0 + 6][ar] = a1.z; Ast[ac0 + 7][ar] = a1.w;
        *(float4*)&Bs[ty][tx * 4] = *(const float4*)&Bw[(size_t)(k0 + ty) * DHEAD + tx * 4];
        __syncthreads();
        #pragma unroll
        for (int kk = 0; kk < 16; kk++) {
            float4 A0 = *(float4*)&Ast[kk][ty * 8];
            float4 A1 = *(float4*)&Ast[kk][ty * 8 + 4];
            float4 B0 = *(float4*)&Bs[kk][tx * 4];
            float a[8] = {A0.x, A0.y, A0.z, A0.w, A1.x, A1.y, A1.z, A1.w};
            float bb[4] = {B0.x, B0.y, B0.z, B0.w};
            #pragma unroll
            for (int i = 0; i < 8; i++)
                #pragma unroll
                for (int j = 0; j < 4; j++)
                    acc[i][j] += a[i] * bb[j];
        }
        __syncthreads();
    }
    #pragma unroll
    for (int i = 0; i < 8; i++)
        *(float4*)&Out[(size_t)(ty * 8 + i) * DHEAD + tx * 4] =
            make_float4(acc[i][0], acc[i][1], acc[i][2], acc[i][3]);
}

// ---------------------------------------------------------------------------
// Flash attention (fused score+softmax+ctx), used when attn need not be output.
// Per block: 128 q-rows, stream K/V in 64-row tiles. 8x4 per thread.
// grid = (16 i-tiles, 64 z), block = 256, dynamic smem = 100 KB
// ---------------------------------------------------------------------------
__global__ __launch_bounds__(256, 2) void flash_kernel(const float* __restrict__ Qp,
                                                       const float* __restrict__ Kp,
                                                       const float* __restrict__ Vp,
                                                       float* __restrict__ Ctx)
{
    extern __shared__ float sm[];
    float* Qst = sm;                  // [64][132]  (e-major, row)
    float* Kst = Qst + 64 * 132;      // [64][68]   (e-major, col)
    float* Vs  = Kst + 64 * 68;       // [64][68]   (k-row, e)
    float* Pst = Vs + 64 * 68;        // [64][132]  (k-col, q-row)

    const int z = blockIdx.y;
    const int b = z >> 4, h = z & 15;
    const int i0 = blockIdx.x * 128;

    const float* Q = Qp + (size_t)z * LL * DHEAD;
    const float* K = Kp + (size_t)z * LL * DHEAD;
    const float* V = Vp + (size_t)z * LL * DHEAD;

    const int tid = threadIdx.x, tx = tid & 15, ty = tid >> 4;

    // Load Q tile (128x64), store transposed
    #pragma unroll
    for (int t = 0; t < 8; t++) {
        int v = tid + t * 256;
        int r = v >> 4, c4 = v & 15;
        float4 q4 = *(const float4*)&Q[(size_t)(i0 + r) * DHEAD + c4 * 4];
        Qst[(c4 * 4 + 0) * 132 + r] = q4.x;
        Qst[(c4 * 4 + 1) * 132 + r] = q4.y;
        Qst[(c4 * 4 + 2) * 132 + r] = q4.z;
        Qst[(c4 * 4 + 3) * 132 + r] = q4.w;
    }

    float Oacc[8][4] = {};
    float m[8], l[8];
    #pragma unroll
    for (int i = 0; i < 8; i++) { m[i] = -1e30f; l[i] = 0.0f; }

    for (int j0 = 0; j0 < LL; j0 += 64) {
        // Load K (transposed) and V tiles
        #pragma unroll
        for (int t = 0; t < 4; t++) {
            int v = tid + t * 256;
            int r = v >> 4, c4 = v & 15;
            float4 k4 = *(const float4*)&K[(size_t)(j0 + r) * DHEAD + c4 * 4];
            Kst[(c4 * 4 + 0) * 68 + r] = k4.x;
            Kst[(c4 * 4 + 1) * 68 + r] = k4.y;
            Kst[(c4 * 4 + 2) * 68 + r] = k4.z;
            Kst[(c4 * 4 + 3) * 68 + r] = k4.w;
            *(float4*)&Vs[r * 68 + c4 * 4] = *(const float4*)&V[(size_t)(j0 + r) * DHEAD + c4 * 4];
        }
        __syncthreads();

        // S = Q K^T
        float s[8][4] = {};
        #pragma unroll 8
        for (int e = 0; e < 64; e++) {
            float4 A0 = *(float4*)&Qst[e * 132 + ty * 8];
            float4 A1 = *(float4*)&Qst[e * 132 + ty * 8 + 4];
            float4 B0 = *(float4*)&Kst[e * 68 + tx * 4];
            float a[8] = {A0.x, A0.y, A0.z, A0.w, A1.x, A1.y, A1.z, A1.w};
            float bb[4] = {B0.x, B0.y, B0.z, B0.w};
            #pragma unroll
            for (int i = 0; i < 8; i++)
                #pragma unroll
                for (int j = 0; j < 4; j++)
                    s[i][j] += a[i] * bb[j];
        }

        // scale + online softmax (rows owned by tx-group of 16 lanes)
        float rmax[8];
        #pragma unroll
        for (int i = 0; i < 8; i++) {
            #pragma unroll
            for (int j = 0; j < 4; j++) s[i][j] *= 0.125f;
            rmax[i] = fmaxf(fmaxf(s[i][0], s[i][1]), fmaxf(s[i][2], s[i][3]));
        }
        #pragma unroll
        for (int o = 1; o < 16; o <<= 1)
            #pragma unroll
            for (int i = 0; i < 8; i++)
                rmax[i] = fmaxf(rmax[i], __shfl_xor_sync(0xffffffffu, rmax[i], o));

        float rsum[8];
        #pragma unroll
        for (int i = 0; i < 8; i++) {
            float newm = fmaxf(m[i], rmax[i]);
            float corr = __expf(m[i] - newm);
            m[i] = newm;
            float su = 0.0f;
            #pragma unroll
            for (int j = 0; j < 4; j++) {
                float p = __expf(s[i][j] - newm);
                s[i][j] = p;
                su += p;
            }
            rsum[i] = su;
            l[i] *= corr;
            #pragma unroll
            for (int j = 0; j < 4; j++) Oacc[i][j] *= corr;
        }
        #pragma unroll
        for (int o = 1; o < 16; o <<= 1)
            #pragma unroll
            for (int i = 0; i < 8; i++)
                rsum[i] += __shfl_xor_sync(0xffffffffu, rsum[i], o);
        #pragma unroll
        for (int i = 0; i < 8; i++) l[i] += rsum[i];

        // Store P transposed: Pst[k-col][q-row]
        #pragma unroll
        for (int j = 0; j < 4; j++)
            #pragma unroll
            for (int i = 0; i < 8; i++)
                Pst[(tx * 4 + j) * 132 + ty * 8 + i] = s[i][j];
        __syncthreads();

        // O += P @ V
        #pragma unroll 8
        for (int kk = 0; kk < 64; kk++) {
            float4 A0 = *(float4*)&Pst[kk * 132 + ty * 8];
            float4 A1 = *(float4*)&Pst[kk * 132 + ty * 8 + 4];
            float4 B0 = *(float4*)&Vs[kk * 68 + tx * 4];
            float a[8] = {A0.x, A0.y, A0.z, A0.w, A1.x, A1.y, A1.z, A1.w};
            float bb[4] = {B0.x, B0.y, B0.z, B0.w};
            #pragma unroll
            for (int i = 0; i < 8; i++)
                #pragma unroll
                for (int j = 0; j < 4; j++)
                    Oacc[i][j] += a[i] * bb[j];
        }
        __syncthreads();
    }

    // normalize + write to ctx[b][q][h*64+e]
    #pragma unroll
    for (int i = 0; i < 8; i++) {
        float inv = 1.0f / l[i];
        int row = i0 + ty * 8 + i;
        *(float4*)&Ctx[((size_t)b * LL + row) * (HH * DHEAD) + h * DHEAD + tx * 4] =
            make_float4(Oacc[i][0] * inv, Oacc[i][1] * inv, Oacc[i][2] * inv, Oacc[i][3] * inv);
    }
}

// ---------------------------------------------------------------------------
// score (materialize path): S[z,i,j] = 0.125 * sum_e Q[z,i,e]*K[z,j,e]
// 128x64 tile. grid=(32 j, 16 i, 64 z), block=256, dyn smem 51.2 KB
// ---------------------------------------------------------------------------
__global__ __launch_bounds__(256) void score_v2(const float* __restrict__ Qp,
                                                const float* __restrict__ Kp,
                                                float* __restrict__ Sout)
{
    extern __shared__ float sm[];
    float* Qst = sm;             // [64][132]
    float* Kst = sm + 64 * 132;  // [64][68]

    const int z = blockIdx.z;
    const int i0 = blockIdx.y * 128, j0 = blockIdx.x * 64;
    const float* Q = Qp + (size_t)z * LL * DHEAD;
    const float* K = Kp + (size_t)z * LL * DHEAD;
    float* S = Sout + (size_t)z * LL * LL;

    const int tid = threadIdx.x, tx = tid & 15, ty = tid >> 4;

    #pragma unroll
    for (int t = 0; t < 8; t++) {
        int v = tid + t * 256;
        int r = v >> 4, c4 = v & 15;
        float4 q4 = *(const float4*)&Q[(size_t)(i0 + r) * DHEAD + c4 * 4];
        Qst[(c4 * 4 + 0) * 132 + r] = q4.x;
        Qst[(c4 * 4 + 1) * 132 + r] = q4.y;
        Qst[(c4 * 4 + 2) * 132 + r] = q4.z;
        Qst[(c4 * 4 + 3) * 132 + r] = q4.w;
    }
    #pragma unroll
    for (int t = 0; t < 4; t++) {
        int v = tid + t * 256;
        int r = v >> 4, c4 = v & 15;
        float4 k4 = *(const float4*)&K[(size_t)(j0 + r) * DHEAD + c4 * 4];
        Kst[(c4 * 4 + 0) * 68 + r] = k4.x;
        Kst[(c4 * 4 + 1) * 68 + r] = k4.y;
        Kst[(c4 * 4 + 2) * 68 + r] = k4.z;
        Kst[(c4 * 4 + 3) * 68 + r] = k4.w;
    }
    __syncthreads();

    float acc[8][4] = {};
    #pragma unroll 8
    for (int e = 0; e < 64; e++) {
        float4 A0 = *(float4*)&Qst[e * 132 + ty * 8];
        float4 A1 = *(float4*)&Qst[e * 132 + ty * 8 + 4];
        float4 B0 = *(float4*)&Kst[e * 68 + tx * 4];
        float a[8] = {A0.x, A0.y, A0.z, A0.w, A1.x, A1.y, A1.z, A1.w};
        float bb[4] = {B0.x, B0.y, B0.z, B0.w};
        #pragma unroll
        for (int i = 0; i < 8; i++)
            #pragma unroll
            for (int j = 0; j < 4; j++)
                acc[i][j] += a[i] * bb[j];
    }
    #pragma unroll
    for (int i = 0; i < 8; i++) {
        int row = i0 + ty * 8 + i;
        *(float4*)&S[(size_t)row * LL + j0 + tx * 4] =
            make_float4(acc[i][0] * 0.125f, acc[i][1] * 0.125f,
                        acc[i][2] * 0.125f, acc[i][3] * 0.125f);
    }
}

// ---------------------------------------------------------------------------
// Row softmax, 2048 elems, in place. grid=(131072), block=256
// ---------------------------------------------------------------------------
__global__ __launch_bounds__(256) void softmax_kernel(float* __restrict__ S)
{
    float4* p4 = (float4*)(S + (size_t)blockIdx.x * LL);
    const int tid = threadIdx.x;
    const int warp = tid >> 5, lane = tid & 31;
    __shared__ float red[8];

    float4 v0 = p4[tid], v1 = p4[tid + 256];
    float m = fmaxf(fmaxf(fmaxf(v0.x, v0.y), fmaxf(v0.z, v0.w)),
                    fmaxf(fmaxf(v1.x, v1.y), fmaxf(v1.z, v1.w)));
    #pragma unroll
    for (int o = 16; o > 0; o >>= 1) m = fmaxf(m, __shfl_xor_sync(0xffffffffu, m, o));
    if (lane == 0) red[warp] = m;
    __syncthreads();
    if (tid < 8) {
        float t = red[tid];
        #pragma unroll
        for (int o = 4; o > 0; o >>= 1) t = fmaxf(t, __shfl_xor_sync(0xffu, t, o));
        if (tid == 0) red[0] = t;
    }
    __syncthreads();
    m = red[0];
    __syncthreads();

    v0.x = __expf(v0.x - m); v0.y = __expf(v0.y - m);
    v0.z = __expf(v0.z - m); v0.w = __expf(v0.w - m);
    v1.x = __expf(v1.x - m); v1.y = __expf(v1.y - m);
    v1.z = __expf(v1.z - m); v1.w = __expf(v1.w - m);
    float s = v0.x + v0.y + v0.z + v0.w + v1.x + v1.y + v1.z + v1.w;
    #pragma unroll
    for (int o = 16; o > 0; o >>= 1) s += __shfl_xor_sync(0xffffffffu, s, o);
    if (lane == 0) red[warp] = s;
    __syncthreads();
    if (tid < 8) {
        float t = red[tid];
        #pragma unroll
        for (int o = 4; o > 0; o >>= 1) t += __shfl_xor_sync(0xffu, t, o);
        if (tid == 0) red[0] = t;
    }
    __syncthreads();
    float inv = 1.0f / red[0];

    v0.x *= inv; v0.y *= inv; v0.z *= inv; v0.w *= inv;
    v1.x *= inv; v1.y *= inv; v1.z *= inv; v1.w *= inv;
    p4[tid] = v0; p4[tid + 256] = v1;
}

// ---------------------------------------------------------------------------
// ctx (materialize path): C = attn @ V per z. 128x64 tile, BK=32.
// grid=(16 i, 1, 64 z), block=256
// ---------------------------------------------------------------------------
__global__ __launch_bounds__(256) void ctx_v2(const float* __restrict__ Sm,
                                              const float* __restrict__ Vp,
                                              float* __restrict__ Ctx)
{
    const int z = blockIdx.z;
    const int b = z >> 4, h = z & 15;
    const int i0 = blockIdx.x * 128;
    const float* A = Sm + (size_t)z * LL * LL;
    const float* V = Vp + (size_t)z * LL * DHEAD;

    __shared__ float Ast[32][132];
    __shared__ float Bs[32][68];

    const int tid = threadIdx.x, tx = tid & 15, ty = tid >> 4;

    float acc[8][4] = {};

    for (int k0 = 0; k0 < LL; k0 += 32) {
        #pragma unroll
        for (int t = 0; t < 4; t++) {
            int v = tid + t * 256;
            int r = v >> 3, c4 = v & 7;
            float4 a4 = *(const float4*)&A[(size_t)(i0 + r) * LL + k0 + c4 * 4];
            Ast[c4 * 4 + 0][r] = a4.x;
            Ast[c4 * 4 + 1][r] = a4.y;
            Ast[c4 * 4 + 2][r] = a4.z;
            Ast[c4 * 4 + 3][r] = a4.w;
        }
        #pragma unroll
        for (int t = 0; t < 2; t++) {
            int v = tid + t * 256;
            int r = v >> 4, c4 = v & 15;
            *(float4*)&Bs[r][c4 * 4] = *(const float4*)&V[(size_t)(k0 + r) * DHEAD + c4 * 4];
        }
        __syncthreads();
        #pragma unroll 8
        for (int kk = 0; kk < 32; kk++) {
            float4 A0 = *(float4*)&Ast[kk][ty * 8];
            float4 A1 = *(float4*)&Ast[kk][ty * 8 + 4];
            float4 B0 = *(float4*)&Bs[kk][tx * 4];
            float a[8] = {A0.x, A0.y, A0.z, A0.w, A1.x, A1.y, A1.z, A1.w};
            float bb[4] = {B0.x, B0.y, B0.z, B0.w};
            #pragma unroll
            for (int i = 0; i < 8; i++)
                #pragma unroll
                for (int j = 0; j < 4; j++)
                    acc[i][j] += a[i] * bb[j];
        }
        __syncthreads();
    }
    #pragma unroll
    for (int i = 0; i < 8; i++) {
        int row = i0 + ty * 8 + i;
        *(float4*)&Ctx[((size_t)b * LL + row) * (HH * DHEAD) + h * DHEAD + tx * 4] =
            make_float4(acc[i][0], acc[i][1], acc[i][2], acc[i][3]);
    }
}

// ---------------------------------------------------------------------------
// out: (8192 x 1024) = ctx @ wo. 128x64 tile, BK=32.
// grid=(16 j, 64 i), block=256
// ---------------------------------------------------------------------------
__global__ __launch_bounds__(256) void out_v2(const float* __restrict__ Ctx,
                                              const float* __restrict__ Wo,
                                              float* __restrict__ Out)
{
    const int i0 = blockIdx.y * 128, j0 = blockIdx.x * 64;
    const int NN = HH * DHEAD; // 1024

    __shared__ float Ast[32][132];
    __shared__ float Bs[32][68];

    const int tid = threadIdx.x, tx = tid & 15, ty = tid >> 4;

    float acc[8][4] = {};

    for (int k0 = 0; k0 < NN; k0 += 32) {
        #pragma unroll
        for (int t = 0; t < 4; t++) {
            int v = tid + t * 256;
            int r = v >> 3, c4 = v & 7;
            float4 a4 = *(const float4*)&Ctx[(size_t)(i0 + r) * NN + k0 + c4 * 4];
            Ast[c4 * 4 + 0][r] = a4.x;
            Ast[c4 * 4 + 1][r] = a4.y;
            Ast[c4 * 4 + 2][r] = a4.z;
            Ast[c4 * 4 + 3][r] = a4.w;
        }
        #pragma unroll
        for (int t = 0; t < 2; t++) {
            int v = tid + t * 256;
            int r = v >> 4, c4 = v & 15;
            *(float4*)&Bs[r][c4 * 4] = *(const float4*)&Wo[(size_t)(k0 + r) * DM + j0 + c4 * 4];
        }
        __syncthreads();
        #pragma unroll 8
        for (int kk = 0; kk < 32; kk++) {
            float4 A0 = *(float4*)&Ast[kk][ty * 8];
            float4 A1 = *(float4*)&Ast[kk][ty * 8 + 4];
            float4 B0 = *(float4*)&Bs[kk][tx * 4];
            float a[8] = {A0.x, A0.y, A0.z, A0.w, A1.x, A1.y, A1.z, A1.w};
            float bb[4] = {B0.x, B0.y, B0.z, B0.w};
            #pragma unroll
            for (int i = 0; i < 8; i++)
                #pragma unroll
                for (int j = 0; j < 4; j++)
                    acc[i][j] += a[i] * bb[j];
        }
        __syncthreads();
    }
    #pragma unroll
    for (int i = 0; i < 8; i++) {
        int row = i0 + ty * 8 + i;
        *(float4*)&Out[(size_t)row * DM + j0 + tx * 4] =
            make_float4(acc[i][0], acc[i][1], acc[i][2], acc[i][3]);
    }
}

// ---------------------------------------------------------------------------
extern "C" void kernel_launch(void* const* d_in, const int* in_sizes, int n_in,
                              void* d_out, int out_size)
{
    const float* q  = (const float*)d_in[0];
    const float* k  = (const float*)d_in[1];
    const float* v  = (const float*)d_in[2];
    const float* wq = (const float*)d_in[3];
    const float* wk = (const float*)d_in[4];
    const float* wv = (const float*)d_in[5];
    const float* wo = (const float*)d_in[6];

    float* out = (float*)d_out;

    const size_t OUT_ELEMS  = (size_t)BB * LL * DM;
    const size_t ATTN_ELEMS = (size_t)BB * HH * LL * LL;

    float *gQ, *gK, *gV, *gCtx;
    cudaGetSymbolAddress((void**)&gQ, g_Q);
    cudaGetSymbolAddress((void**)&gK, g_K);
    cudaGetSymbolAddress((void**)&gV, g_V);
    cudaGetSymbolAddress((void**)&gCtx, g_ctx);

    const bool need_attn = ((size_t)(unsigned)out_size >= OUT_ELEMS + ATTN_ELEMS);

    dim3 blk(256);
    proj_v2<<<dim3(LL / 128, HH, BB), blk>>>(q, wq, gQ);
    proj_v2<<<dim3(LL / 128, HH, BB), blk>>>(k, wk, gK);
    proj_v2<<<dim3(LL / 128, HH, BB), blk>>>(v, wv, gV);

    if (need_attn) {
        float* attn = out + OUT_ELEMS;
        const int score_smem = (64 * 132 + 64 * 68) * 4; // 51200 B
        cudaFuncSetAttribute(score_v2, cudaFuncAttributeMaxDynamicSharedMemorySize, score_smem);
        score_v2<<<dim3(LL / 64, LL / 128, BB * HH), blk, score_smem>>>(gQ, gK, attn);
        softmax_kernel<<<dim3(BB * HH * LL), blk>>>(attn);
        ctx_v2<<<dim3(LL / 128, 1, BB * HH), blk>>>(attn, gV, gCtx);
    } else {
        const int flash_smem = (2 * 64 * 132 + 2 * 64 * 68) * 4; // 102400 B
        cudaFuncSetAttribute(flash_kernel, cudaFuncAttributeMaxDynamicSharedMemorySize, flash_smem);
        flash_kernel<<<dim3(LL / 128, BB * HH), blk, flash_smem>>>(gQ, gK, gV, gCtx);
    }

    out_v2<<<dim3(DM / 64, (BB * LL) / 128), blk>>>(gCtx, wo, out);
}

// round 4
// speedup vs baseline: 1.7505x; 1.4302x over previous
#include <cuda_runtime.h>
#include <cuda_bf16.h>
#include <cstdint>

#define BB 4
#define HH 16
#define LL 2048
#define DM 1024
#define DHEAD 64

// Scratch (__device__ globals; allocation-free rule)
__device__ float g_Q[(size_t)BB * HH * LL * DHEAD];
__device__ float g_K[(size_t)BB * HH * LL * DHEAD];
__device__ float g_V[(size_t)BB * HH * LL * DHEAD];
__device__ float g_ctx[(size_t)BB * LL * (HH * DHEAD)];

// ===========================================================================
// mma.sync bf16 helpers (m16n8k16, row.col, f32 accum) — base-ISA tensor path
// ===========================================================================
__device__ __forceinline__ void mma_bf16(float* c,
                                         uint32_t a0, uint32_t a1, uint32_t a2, uint32_t a3,
                                         uint32_t b0, uint32_t b1)
{
    asm volatile(
        "mma.sync.aligned.m16n8k16.row.col.f32.bf16.bf16.f32 "
        "{%0,%1,%2,%3}, {%4,%5,%6,%7}, {%8,%9}, {%0,%1,%2,%3};"
        : "+f"(c[0]), "+f"(c[1]), "+f"(c[2]), "+f"(c[3])
        : "r"(a0), "r"(a1), "r"(a2), "r"(a3), "r"(b0), "r"(b1));
}

// 3-term split-bf16 product: Ahi*Bhi + Ahi*Blo + Alo*Bhi
__device__ __forceinline__ void mma3(float* c,
                                     const uint32_t* ah, const uint32_t* al,
                                     const uint32_t* bh, const uint32_t* bl)
{
    mma_bf16(c, ah[0], ah[1], ah[2], ah[3], bh[0], bh[1]);
    mma_bf16(c, ah[0], ah[1], ah[2], ah[3], bl[0], bl[1]);
    mma_bf16(c, al[0], al[1], al[2], al[3], bh[0], bh[1]);
}

// Split two fp32 into packed bf16x2 hi/lo planes
__device__ __forceinline__ void split_pair(float x, float y, uint32_t& h, uint32_t& l)
{
    __nv_bfloat16 hx = __float2bfloat16(x);
    __nv_bfloat16 hy = __float2bfloat16(y);
    __nv_bfloat162 hp = __halves2bfloat162(hx, hy);
    __nv_bfloat162 lp = __halves2bfloat162(__float2bfloat16(x - __bfloat162float(hx)),
                                           __float2bfloat16(y - __bfloat162float(hy)));
    h = *(uint32_t*)&hp;
    l = *(uint32_t*)&lp;
}
__device__ __forceinline__ void split_one(float x, __nv_bfloat16& h, __nv_bfloat16& l)
{
    h = __float2bfloat16(x);
    l = __float2bfloat16(x - __bfloat162float(h));
}

// ===========================================================================
// score_mma: S[z,i,j] = 0.125 * sum_e Q[z,i,e] K[z,j,e]
// CTA: 128x128 tile. 8 warps (2x4), warp tile 64x32. K=64 (4 ksteps of 16).
// grid = (16 j, 16 i, 64 z), block = 256, dyn smem 73728 B
// ===========================================================================
__global__ __launch_bounds__(256) void score_mma(const float* __restrict__ Qp,
                                                 const float* __restrict__ Kp,
                                                 float* __restrict__ Sout)
{
    extern __shared__ char smraw[];
    __nv_bfloat16* QH = (__nv_bfloat16*)smraw;        // [128][72]
    __nv_bfloat16* QL = QH + 128 * 72;
    __nv_bfloat16* KH = QL + 128 * 72;
    __nv_bfloat16* KL = KH + 128 * 72;
    float* Ssm = (float*)smraw;                       // epilogue reuse [128][132]

    const int tid = threadIdx.x, wid = tid >> 5, lane = tid & 31;
    const int wm = (wid >> 2) * 64, wn = (wid & 3) * 32;
    const int z = blockIdx.z, i0 = blockIdx.y * 128, j0 = blockIdx.x * 128;
    const float* Q = Qp + (size_t)z * LL * DHEAD;
    const float* K = Kp + (size_t)z * LL * DHEAD;

    // Fill split planes
    #pragma unroll
    for (int t = 0; t < 8; t++) {
        int v = tid + t * 256;
        int r = v >> 4, c = (v & 15) * 4;
        float4 qv = *(const float4*)&Q[(size_t)(i0 + r) * DHEAD + c];
        uint32_t h0, l0, h1, l1;
        split_pair(qv.x, qv.y, h0, l0);
        split_pair(qv.z, qv.w, h1, l1);
        *(uint32_t*)&QH[r * 72 + c] = h0; *(uint32_t*)&QH[r * 72 + c + 2] = h1;
        *(uint32_t*)&QL[r * 72 + c] = l0; *(uint32_t*)&QL[r * 72 + c + 2] = l1;
        float4 kv = *(const float4*)&K[(size_t)(j0 + r) * DHEAD + c];
        split_pair(kv.x, kv.y, h0, l0);
        split_pair(kv.z, kv.w, h1, l1);
        *(uint32_t*)&KH[r * 72 + c] = h0; *(uint32_t*)&KH[r * 72 + c + 2] = h1;
        *(uint32_t*)&KL[r * 72 + c] = l0; *(uint32_t*)&KL[r * 72 + c + 2] = l1;
    }
    __syncthreads();

    float acc[4][4][4] = {};
    const int qr = lane >> 2, qc = (lane & 3) * 2;

    #pragma unroll
    for (int ks = 0; ks < 4; ks++) {
        const int k0 = ks * 16;
        uint32_t bh[4][2], bl[4][2];
        #pragma unroll
        for (int jn = 0; jn < 4; jn++) {
            int n = wn + jn * 8 + qr;
            bh[jn][0] = *(uint32_t*)&KH[n * 72 + k0 + qc];
            bh[jn][1] = *(uint32_t*)&KH[n * 72 + k0 + 8 + qc];
            bl[jn][0] = *(uint32_t*)&KL[n * 72 + k0 + qc];
            bl[jn][1] = *(uint32_t*)&KL[n * 72 + k0 + 8 + qc];
        }
        #pragma unroll
        for (int im = 0; im < 4; im++) {
            int m = wm + im * 16 + qr;
            uint32_t ah[4], al[4];
            ah[0] = *(uint32_t*)&QH[m * 72 + k0 + qc];
            ah[1] = *(uint32_t*)&QH[(m + 8) * 72 + k0 + qc];
            ah[2] = *(uint32_t*)&QH[m * 72 + k0 + 8 + qc];
            ah[3] = *(uint32_t*)&QH[(m + 8) * 72 + k0 + 8 + qc];
            al[0] = *(uint32_t*)&QL[m * 72 + k0 + qc];
            al[1] = *(uint32_t*)&QL[(m + 8) * 72 + k0 + qc];
            al[2] = *(uint32_t*)&QL[m * 72 + k0 + 8 + qc];
            al[3] = *(uint32_t*)&QL[(m + 8) * 72 + k0 + 8 + qc];
            #pragma unroll
            for (int jn = 0; jn < 4; jn++)
                mma3(acc[im][jn], ah, al, bh[jn], bl[jn]);
        }
    }
    __syncthreads();

    // stage scaled to smem
    #pragma unroll
    for (int im = 0; im < 4; im++) {
        int row = wm + im * 16 + qr;
        #pragma unroll
        for (int jn = 0; jn < 4; jn++) {
            int col = wn + jn * 8 + qc;
            *(float2*)&Ssm[row * 132 + col] =
                make_float2(acc[im][jn][0] * 0.125f, acc[im][jn][1] * 0.125f);
            *(float2*)&Ssm[(row + 8) * 132 + col] =
                make_float2(acc[im][jn][2] * 0.125f, acc[im][jn][3] * 0.125f);
        }
    }
    __syncthreads();

    float* S = Sout + (size_t)z * LL * LL;
    #pragma unroll
    for (int t = 0; t < 16; t++) {
        int v = tid + t * 256;
        int r = v >> 5, c = (v & 31) * 4;
        *(float4*)&S[(size_t)(i0 + r) * LL + j0 + c] = *(float4*)&Ssm[r * 132 + c];
    }
}

// ===========================================================================
// ctx_mma: C[z] = attn[z](2048x2048) @ V[z](2048x64), kv streamed in 64-chunks
// CTA: 128 rows x 64 e. 8 warps (4x2), warp tile 32x32.
// grid = (16 i, 64 z), block = 256, dyn smem 55296 B
// ===========================================================================
__global__ __launch_bounds__(256) void ctx_mma(const float* __restrict__ Sm,
                                               const float* __restrict__ Vp,
                                               float* __restrict__ Ctx)
{
    extern __shared__ char smraw[];
    __nv_bfloat16* AH = (__nv_bfloat16*)smraw;     // [128][72]
    __nv_bfloat16* AL = AH + 128 * 72;
    __nv_bfloat16* TH = AL + 128 * 72;             // V^T [64 e][72]
    __nv_bfloat16* TL = TH + 64 * 72;
    float* Cs = (float*)smraw;                     // epilogue reuse [128][68]

    const int tid = threadIdx.x, wid = tid >> 5, lane = tid & 31;
    const int wm = (wid >> 1) * 32, wn = (wid & 1) * 32;
    const int z = blockIdx.y, b = z >> 4, h = z & 15;
    const int i0 = blockIdx.x * 128;
    const float* A = Sm + (size_t)z * LL * LL;
    const float* V = Vp + (size_t)z * LL * DHEAD;

    const int qr = lane >> 2, qc = (lane & 3) * 2;
    float acc[2][4][4] = {};

    for (int c = 0; c < 32; c++) {
        const int kv0 = c * 64;
        // attn tile 128x64 -> split planes
        #pragma unroll
        for (int t = 0; t < 8; t++) {
            int v = tid + t * 256;
            int r = v >> 4, cc = (v & 15) * 4;
            float4 av = *(const float4*)&A[(size_t)(i0 + r) * LL + kv0 + cc];
            uint32_t h0, l0, h1, l1;
            split_pair(av.x, av.y, h0, l0);
            split_pair(av.z, av.w, h1, l1);
            *(uint32_t*)&AH[r * 72 + cc] = h0; *(uint32_t*)&AH[r * 72 + cc + 2] = h1;
            *(uint32_t*)&AL[r * 72 + cc] = l0; *(uint32_t*)&AL[r * 72 + cc + 2] = l1;
        }
        // V chunk 64x64 -> transposed split planes TH/TL[e][kv]
        #pragma unroll
        for (int t = 0; t < 4; t++) {
            int v = tid + t * 256;
            int r = v >> 4, cc = (v & 15) * 4;  // r = kv row, cc = e base
            float4 vv = *(const float4*)&V[(size_t)(kv0 + r) * DHEAD + cc];
            float vals[4] = {vv.x, vv.y, vv.z, vv.w};
            #pragma unroll
            for (int jj = 0; jj < 4; jj++) {
                __nv_bfloat16 hh, ll;
                split_one(vals[jj], hh, ll);
                TH[(cc + jj) * 72 + r] = hh;
                TL[(cc + jj) * 72 + r] = ll;
            }
        }
        __syncthreads();

        #pragma unroll
        for (int ks = 0; ks < 4; ks++) {
            const int k0 = ks * 16;
            uint32_t bh[4][2], bl[4][2];
            #pragma unroll
            for (int jn = 0; jn < 4; jn++) {
                int n = wn + jn * 8 + qr;
                bh[jn][0] = *(uint32_t*)&TH[n * 72 + k0 + qc];
                bh[jn][1] = *(uint32_t*)&TH[n * 72 + k0 + 8 + qc];
                bl[jn][0] = *(uint32_t*)&TL[n * 72 + k0 + qc];
                bl[jn][1] = *(uint32_t*)&TL[n * 72 + k0 + 8 + qc];
            }
            #pragma unroll
            for (int im = 0; im < 2; im++) {
                int m = wm + im * 16 + qr;
                uint32_t ah[4], al[4];
                ah[0] = *(uint32_t*)&AH[m * 72 + k0 + qc];
                ah[1] = *(uint32_t*)&AH[(m + 8) * 72 + k0 + qc];
                ah[2] = *(uint32_t*)&AH[m * 72 + k0 + 8 + qc];
                ah[3] = *(uint32_t*)&AH[(m + 8) * 72 + k0 + 8 + qc];
                al[0] = *(uint32_t*)&AL[m * 72 + k0 + qc];
                al[1] = *(uint32_t*)&AL[(m + 8) * 72 + k0 + qc];
                al[2] = *(uint32_t*)&AL[m * 72 + k0 + 8 + qc];
                al[3] = *(uint32_t*)&AL[(m + 8) * 72 + k0 + 8 + qc];
                #pragma unroll
                for (int jn = 0; jn < 4; jn++)
                    mma3(acc[im][jn], ah, al, bh[jn], bl[jn]);
            }
        }
        __syncthreads();
    }

    // stage + coalesced write to ctx[b][q][h*64+e]
    #pragma unroll
    for (int im = 0; im < 2; im++) {
        int row = wm + im * 16 + qr;
        #pragma unroll
        for (int jn = 0; jn < 4; jn++) {
            int col = wn + jn * 8 + qc;
            *(float2*)&Cs[row * 68 + col] = make_float2(acc[im][jn][0], acc[im][jn][1]);
            *(float2*)&Cs[(row + 8) * 68 + col] = make_float2(acc[im][jn][2], acc[im][jn][3]);
        }
    }
    __syncthreads();
    #pragma unroll
    for (int t = 0; t < 8; t++) {
        int v = tid + t * 256;
        int r = v >> 4, cc = (v & 15) * 4;
        *(float4*)&Ctx[((size_t)b * LL + i0 + r) * (HH * DHEAD) + h * DHEAD + cc] =
            *(float4*)&Cs[r * 68 + cc];
    }
}

// ===========================================================================
// proj_mma: Out[b,h,s,e] = sum_d X[b,s,d] W[h,d,e]
// CTA: 128 rows x 64 e; d streamed in 32-chunks. 8 warps (4x2), warp 32x32.
// grid = (16, 16, 4), block = 256, dyn smem 34816 B
// ===========================================================================
__global__ __launch_bounds__(256) void proj_mma(const float* __restrict__ X,
                                                const float* __restrict__ W,
                                                float* __restrict__ O)
{
    extern __shared__ char smraw[];
    __nv_bfloat16* XH = (__nv_bfloat16*)smraw;     // [128][40]
    __nv_bfloat16* XL = XH + 128 * 40;
    __nv_bfloat16* TH = XL + 128 * 40;             // W^T [64 e][40]
    __nv_bfloat16* TL = TH + 64 * 40;
    float* Cs = (float*)smraw;                     // [128][68]

    const int tid = threadIdx.x, wid = tid >> 5, lane = tid & 31;
    const int wm = (wid >> 1) * 32, wn = (wid & 1) * 32;
    const int b = blockIdx.z, h = blockIdx.y, i0 = blockIdx.x * 128;
    const float* A  = X + (size_t)b * LL * DM;
    const float* Bw = W + (size_t)h * DM * DHEAD;
    float* Out = O + ((size_t)(b * HH + h) * LL + i0) * DHEAD;

    const int qr = lane >> 2, qc = (lane & 3) * 2;
    float acc[2][4][4] = {};

    for (int c = 0; c < 32; c++) {
        const int k0g = c * 32;
        #pragma unroll
        for (int t = 0; t < 4; t++) {
            int v = tid + t * 256;
            int r = v >> 3, cc = (v & 7) * 4;
            float4 xv = *(const float4*)&A[(size_t)(i0 + r) * DM + k0g + cc];
            uint32_t h0, l0, h1, l1;
            split_pair(xv.x, xv.y, h0, l0);
            split_pair(xv.z, xv.w, h1, l1);
            *(uint32_t*)&XH[r * 40 + cc] = h0; *(uint32_t*)&XH[r * 40 + cc + 2] = h1;
            *(uint32_t*)&XL[r * 40 + cc] = l0; *(uint32_t*)&XL[r * 40 + cc + 2] = l1;
        }
        #pragma unroll
        for (int t = 0; t < 2; t++) {
            int v = tid + t * 256;
            int r = v >> 4, cc = (v & 15) * 4; // r = d row, cc = e base
            float4 wv = *(const float4*)&Bw[(size_t)(k0g + r) * DHEAD + cc];
            float vals[4] = {wv.x, wv.y, wv.z, wv.w};
            #pragma unroll
            for (int jj = 0; jj < 4; jj++) {
                __nv_bfloat16 hh, ll;
                split_one(vals[jj], hh, ll);
                TH[(cc + jj) * 40 + r] = hh;
                TL[(cc + jj) * 40 + r] = ll;
            }
        }
        __syncthreads();

        #pragma unroll
        for (int ks = 0; ks < 2; ks++) {
            const int k0 = ks * 16;
            uint32_t bh[4][2], bl[4][2];
            #pragma unroll
            for (int jn = 0; jn < 4; jn++) {
                int n = wn + jn * 8 + qr;
                bh[jn][0] = *(uint32_t*)&TH[n * 40 + k0 + qc];
                bh[jn][1] = *(uint32_t*)&TH[n * 40 + k0 + 8 + qc];
                bl[jn][0] = *(uint32_t*)&TL[n * 40 + k0 + qc];
                bl[jn][1] = *(uint32_t*)&TL[n * 40 + k0 + 8 + qc];
            }
            #pragma unroll
            for (int im = 0; im < 2; im++) {
                int m = wm + im * 16 + qr;
                uint32_t ah[4], al[4];
                ah[0] = *(uint32_t*)&XH[m * 40 + k0 + qc];
                ah[1] = *(uint32_t*)&XH[(m + 8) * 40 + k0 + qc];
                ah[2] = *(uint32_t*)&XH[m * 40 + k0 + 8 + qc];
                ah[3] = *(uint32_t*)&XH[(m + 8) * 40 + k0 + 8 + qc];
                al[0] = *(uint32_t*)&XL[m * 40 + k0 + qc];
                al[1] = *(uint32_t*)&XL[(m + 8) * 40 + k0 + qc];
                al[2] = *(uint32_t*)&XL[m * 40 + k0 + 8 + qc];
                al[3] = *(uint32_t*)&XL[(m + 8) * 40 + k0 + 8 + qc];
                #pragma unroll
                for (int jn = 0; jn < 4; jn++)
                    mma3(acc[im][jn], ah, al, bh[jn], bl[jn]);
            }
        }
        __syncthreads();
    }

    #pragma unroll
    for (int im = 0; im < 2; im++) {
        int row = wm + im * 16 + qr;
        #pragma unroll
        for (int jn = 0; jn < 4; jn++) {
            int col = wn + jn * 8 + qc;
            *(float2*)&Cs[row * 68 + col] = make_float2(acc[im][jn][0], acc[im][jn][1]);
            *(float2*)&Cs[(row + 8) * 68 + col] = make_float2(acc[im][jn][2], acc[im][jn][3]);
        }
    }
    __syncthreads();
    #pragma unroll
    for (int t = 0; t < 8; t++) {
        int v = tid + t * 256;
        int r = v >> 4, cc = (v & 15) * 4;
        *(float4*)&Out[(size_t)r * DHEAD + cc] = *(float4*)&Cs[r * 68 + cc];
    }
}

// ===========================================================================
// out_mma: Out(8192x1024) = Ctx(8192x1024) @ Wo(1024x1024)
// CTA: 128 rows x 64 cols; k streamed in 32-chunks. grid = (16 j, 64 i)
// ===========================================================================
__global__ __launch_bounds__(256) void out_mma(const float* __restrict__ Ctx,
                                               const float* __restrict__ Wo,
                                               float* __restrict__ Out)
{
    extern __shared__ char smraw[];
    __nv_bfloat16* XH = (__nv_bfloat16*)smraw;     // [128][40]
    __nv_bfloat16* XL = XH + 128 * 40;
    __nv_bfloat16* TH = XL + 128 * 40;             // Wo^T [64 n][40]
    __nv_bfloat16* TL = TH + 64 * 40;
    float* Cs = (float*)smraw;

    const int tid = threadIdx.x, wid = tid >> 5, lane = tid & 31;
    const int wm = (wid >> 1) * 32, wn = (wid & 1) * 32;
    const int i0 = blockIdx.y * 128, j0 = blockIdx.x * 64;
    const int NN = HH * DHEAD; // 1024

    const int qr = lane >> 2, qc = (lane & 3) * 2;
    float acc[2][4][4] = {};

    for (int c = 0; c < 32; c++) {
        const int k0g = c * 32;
        #pragma unroll
        for (int t = 0; t < 4; t++) {
            int v = tid + t * 256;
            int r = v >> 3, cc = (v & 7) * 4;
            float4 xv = *(const float4*)&Ctx[(size_t)(i0 + r) * NN + k0g + cc];
            uint32_t h0, l0, h1, l1;
            split_pair(xv.x, xv.y, h0, l0);
            split_pair(xv.z, xv.w, h1, l1);
            *(uint32_t*)&XH[r * 40 + cc] = h0; *(uint32_t*)&XH[r * 40 + cc + 2] = h1;
            *(uint32_t*)&XL[r * 40 + cc] = l0; *(uint32_t*)&XL[r * 40 + cc + 2] = l1;
        }
        #pragma unroll
        for (int t = 0; t < 2; t++) {
            int v = tid + t * 256;
            int r = v >> 4, cc = (v & 15) * 4;
            float4 wv = *(const float4*)&Wo[(size_t)(k0g + r) * DM + j0 + cc];
            float vals[4] = {wv.x, wv.y, wv.z, wv.w};
            #pragma unroll
            for (int jj = 0; jj < 4; jj++) {
                __nv_bfloat16 hh, ll;
                split_one(vals[jj], hh, ll);
                TH[(cc + jj) * 40 + r] = hh;
                TL[(cc + jj) * 40 + r] = ll;
            }
        }
        __syncthreads();

        #pragma unroll
        for (int ks = 0; ks < 2; ks++) {
            const int k0 = ks * 16;
            uint32_t bh[4][2], bl[4][2];
            #pragma unroll
            for (int jn = 0; jn < 4; jn++) {
                int n = wn + jn * 8 + qr;
                bh[jn][0] = *(uint32_t*)&TH[n * 40 + k0 + qc];
                bh[jn][1] = *(uint32_t*)&TH[n * 40 + k0 + 8 + qc];
                bl[jn][0] = *(uint32_t*)&TL[n * 40 + k0 + qc];
                bl[jn][1] = *(uint32_t*)&TL[n * 40 + k0 + 8 + qc];
            }
            #pragma unroll
            for (int im = 0; im < 2; im++) {
                int m = wm + im * 16 + qr;
                uint32_t ah[4], al[4];
                ah[0] = *(uint32_t*)&XH[m * 40 + k0 + qc];
                ah[1] = *(uint32_t*)&XH[(m + 8) * 40 + k0 + qc];
                ah[2] = *(uint32_t*)&XH[m * 40 + k0 + 8 + qc];
                ah[3] = *(uint32_t*)&XH[(m + 8) * 40 + k0 + 8 + qc];
                al[0] = *(uint32_t*)&XL[m * 40 + k0 + qc];
                al[1] = *(uint32_t*)&XL[(m + 8) * 40 + k0 + qc];
                al[2] = *(uint32_t*)&XL[m * 40 + k0 + 8 + qc];
                al[3] = *(uint32_t*)&XL[(m + 8) * 40 + k0 + 8 + qc];
                #pragma unroll
                for (int jn = 0; jn < 4; jn++)
                    mma3(acc[im][jn], ah, al, bh[jn], bl[jn]);
            }
        }
        __syncthreads();
    }

    #pragma unroll
    for (int im = 0; im < 2; im++) {
        int row = wm + im * 16 + qr;
        #pragma unroll
        for (int jn = 0; jn < 4; jn++) {
            int col = wn + jn * 8 + qc;
            *(float2*)&Cs[row * 68 + col] = make_float2(acc[im][jn][0], acc[im][jn][1]);
            *(float2*)&Cs[(row + 8) * 68 + col] = make_float2(acc[im][jn][2], acc[im][jn][3]);
        }
    }
    __syncthreads();
    #pragma unroll
    for (int t = 0; t < 8; t++) {
        int v = tid + t * 256;
        int r = v >> 4, cc = (v & 15) * 4;
        *(float4*)&Out[(size_t)(i0 + r) * DM + j0 + cc] = *(float4*)&Cs[r * 68 + cc];
    }
}

// ===========================================================================
// Row softmax, 2048 elems, in place. grid=(131072), block=256
// ===========================================================================
__global__ __launch_bounds__(256) void softmax_kernel(float* __restrict__ S)
{
    float4* p4 = (float4*)(S + (size_t)blockIdx.x * LL);
    const int tid = threadIdx.x;
    const int warp = tid >> 5, lane = tid & 31;
    __shared__ float red[8];

    float4 v0 = p4[tid], v1 = p4[tid + 256];
    float m = fmaxf(fmaxf(fmaxf(v0.x, v0.y), fmaxf(v0.z, v0.w)),
                    fmaxf(fmaxf(v1.x, v1.y), fmaxf(v1.z, v1.w)));
    #pragma unroll
    for (int o = 16; o > 0; o >>= 1) m = fmaxf(m, __shfl_xor_sync(0xffffffffu, m, o));
    if (lane == 0) red[warp] = m;
    __syncthreads();
    if (tid < 8) {
        float t = red[tid];
        #pragma unroll
        for (int o = 4; o > 0; o >>= 1) t = fmaxf(t, __shfl_xor_sync(0xffu, t, o));
        if (tid == 0) red[0] = t;
    }
    __syncthreads();
    m = red[0];
    __syncthreads();

    v0.x = __expf(v0.x - m); v0.y = __expf(v0.y - m);
    v0.z = __expf(v0.z - m); v0.w = __expf(v0.w - m);
    v1.x = __expf(v1.x - m); v1.y = __expf(v1.y - m);
    v1.z = __expf(v1.z - m); v1.w = __expf(v1.w - m);
    float s = v0.x + v0.y + v0.z + v0.w + v1.x + v1.y + v1.z + v1.w;
    #pragma unroll
    for (int o = 16; o > 0; o >>= 1) s += __shfl_xor_sync(0xffffffffu, s, o);
    if (lane == 0) red[warp] = s;
    __syncthreads();
    if (tid < 8) {
        float t = red[tid];
        #pragma unroll
        for (int o = 4; o > 0; o >>= 1) t += __shfl_xor_sync(0xffu, t, o);
        if (tid == 0) red[0] = t;
    }
    __syncthreads();
    float inv = 1.0f / red[0];

    v0.x *= inv; v0.y *= inv; v0.z *= inv; v0.w *= inv;
    v1.x *= inv; v1.y *= inv; v1.z *= inv; v1.w *= inv;
    p4[tid] = v0; p4[tid + 256] = v1;
}

// ===========================================================================
extern "C" void kernel_launch(void* const* d_in, const int* in_sizes, int n_in,
                              void* d_out, int out_size)
{
    const float* q  = (const float*)d_in[0];
    const float* k  = (const float*)d_in[1];
    const float* v  = (const float*)d_in[2];
    const float* wq = (const float*)d_in[3];
    const float* wk = (const float*)d_in[4];
    const float* wv = (const float*)d_in[5];
    const float* wo = (const float*)d_in[6];

    float* out = (float*)d_out;
    const size_t OUT_ELEMS = (size_t)BB * LL * DM;

    float *gQ, *gK, *gV, *gCtx;
    cudaGetSymbolAddress((void**)&gQ, g_Q);
    cudaGetSymbolAddress((void**)&gK, g_K);
    cudaGetSymbolAddress((void**)&gV, g_V);
    cudaGetSymbolAddress((void**)&gCtx, g_ctx);

    float* attn = out + OUT_ELEMS;

    dim3 blk(256);

    const int proj_smem = 34816;
    cudaFuncSetAttribute(proj_mma, cudaFuncAttributeMaxDynamicSharedMemorySize, proj_smem);
    proj_mma<<<dim3(LL / 128, HH, BB), blk, proj_smem>>>(q, wq, gQ);
    proj_mma<<<dim3(LL / 128, HH, BB), blk, proj_smem>>>(k, wk, gK);
    proj_mma<<<dim3(LL / 128, HH, BB), blk, proj_smem>>>(v, wv, gV);

    const int score_smem = 73728;
    cudaFuncSetAttribute(score_mma, cudaFuncAttributeMaxDynamicSharedMemorySize, score_smem);
    score_mma<<<dim3(LL / 128, LL / 128, BB * HH), blk, score_smem>>>(gQ, gK, attn);

    softmax_kernel<<<dim3(BB * HH * LL), blk>>>(attn);

    const int ctx_smem = 55296;
    cudaFuncSetAttribute(ctx_mma, cudaFuncAttributeMaxDynamicSharedMemorySize, ctx_smem);
    ctx_mma<<<dim3(LL / 128, BB * HH), blk, ctx_smem>>>(attn, gV, gCtx);

    const int out_smem = 34816;
    cudaFuncSetAttribute(out_mma, cudaFuncAttributeMaxDynamicSharedMemorySize, out_smem);
    out_mma<<<dim3(DM / 64, (BB * LL) / 128), blk, out_smem>>>(gCtx, wo, out);
}